// round 2
// baseline (speedup 1.0000x reference)
#include <cuda_runtime.h>

#define PDIM     512
#define TILE     128
#define KCHUNK   16
#define NTHREADS 256

typedef unsigned long long u64;

__device__ __forceinline__ float clamp01f(float v) {
    return fminf(fmaxf(v, 0.0f), 1.0f);
}

__device__ __forceinline__ u64 pack2(float lo, float hi) {
    u64 r;
    asm("mov.b64 %0, {%1, %2};" : "=l"(r) : "f"(lo), "f"(hi));
    return r;
}

__device__ __forceinline__ u64 fma2(u64 a, u64 b, u64 c) {
    u64 d;
    asm("fma.rn.f32x2 %0, %1, %2, %3;" : "=l"(d) : "l"(a), "l"(b), "l"(c));
    return d;
}

// out[b, img, p, q] = sum_k u_k(p) * h_k(q)   (see R1 derivation; math unchanged)
__global__ __launch_bounds__(NTHREADS, 2)
void hilbert_raster_kernel(const float* __restrict__ iv00,
                           const float* __restrict__ iv01,
                           float* __restrict__ out)
{
    __shared__ float Xs[64], Ys[64];
    __shared__ u64   Us2[KCHUNK][TILE];  // (u,u) duplicated pairs, k-major
    __shared__ float Hs[KCHUNK][TILE];   // hor factors, k-major (natural f32x2 pairs)

    const int t   = threadIdx.x;
    const int z   = blockIdx.z;      // batch*2 + img
    const int b   = z >> 1;
    const int img = z & 1;
    const int q0  = blockIdx.x * TILE;
    const int p0  = blockIdx.y * TILE;

    const float INV_SIDE = 325.94932345220167f;  // 1024/pi

    if (t < 64) {
        const int k = t;
        float X = 1e9f, Y = -1e9f;
        if (img == 0) {
            if (k < 32) {
                X = iv00[(b * 32 + k) * 2 + 0] * INV_SIDE;
                Y = iv00[(b * 32 + k) * 2 + 1] * INV_SIDE;
            } else {
                X = iv01[(b * 32 + (k - 32)) * 2 + 1] * INV_SIDE - 512.0f;
                Y = iv01[(b * 32 + (k - 32)) * 2 + 0] * INV_SIDE;
            }
        } else if (k < 32) {
            X = iv00[(b * 32 + k) * 2 + 0] * INV_SIDE;
            Y = iv00[(b * 32 + k) * 2 + 1] * INV_SIDE;
        }
        Xs[k] = X;
        Ys[k] = Y;
    }

    const int tx = t & 15;   // q direction
    const int ty = t >> 4;   // p direction

    u64 acc[8][4];
    #pragma unroll
    for (int i = 0; i < 8; ++i)
        #pragma unroll
        for (int j = 0; j < 4; ++j)
            acc[i][j] = 0ull;

    const int Keff = (img == 0) ? 64 : 32;

    for (int kb = 0; kb < Keff; kb += KCHUNK) {
        __syncthreads();
        // ---- generate factor tiles for k in [kb, kb+KCHUNK) ----
        #pragma unroll
        for (int it = 0; it < (KCHUNK * TILE) / NTHREADS; ++it) {
            int idx = t + it * NTHREADS;
            int k = idx >> 7;            // TILE == 128
            int j = idx & (TILE - 1);
            float X = Xs[kb + k];
            float Y = Ys[kb + k];
            float fq = (float)(q0 + j);
            float fp = (float)(p0 + j);
            float u, h;
            if (img == 0) {
                h = clamp01f(fminf(fq + 1.0f - X, Y - fq));
                u = clamp01f(fminf(512.0f - fp - Y, X + 1.0f + fp));
            } else {
                h = clamp01f(fq + 1.0f - X);
                u = clamp01f(Y - 511.0f + fp);
            }
            Us2[k][j] = pack2(u, u);
            Hs[k][j]  = h;
        }
        __syncthreads();

        // ---- rank-KCHUNK update, packed f32x2 FMAs ----
        #pragma unroll
        for (int k = 0; k < KCHUNK; ++k) {
            ulonglong2 ua = *reinterpret_cast<const ulonglong2*>(&Us2[k][ty * 4]);
            ulonglong2 ub = *reinterpret_cast<const ulonglong2*>(&Us2[k][ty * 4 + 2]);
            ulonglong2 uc = *reinterpret_cast<const ulonglong2*>(&Us2[k][ty * 4 + 64]);
            ulonglong2 ud = *reinterpret_cast<const ulonglong2*>(&Us2[k][ty * 4 + 66]);
            ulonglong2 h01 = *reinterpret_cast<const ulonglong2*>(&Hs[k][tx * 4]);
            ulonglong2 h23 = *reinterpret_cast<const ulonglong2*>(&Hs[k][tx * 4 + 64]);
            u64 u2[8] = {ua.x, ua.y, ub.x, ub.y, uc.x, uc.y, ud.x, ud.y};
            u64 h2[4] = {h01.x, h01.y, h23.x, h23.y};
            #pragma unroll
            for (int i = 0; i < 8; ++i)
                #pragma unroll
                for (int j = 0; j < 4; ++j)
                    acc[i][j] = fma2(u2[i], h2[j], acc[i][j]);
        }
    }

    // ---- store 8x8 per thread (as 8x4 pairs), coalesced 16B stores ----
    const size_t base = (size_t)z * PDIM * PDIM;
    #pragma unroll
    for (int i = 0; i < 8; ++i) {
        int p = p0 + ty * 4 + (i & 3) + ((i >= 4) ? 64 : 0);
        u64* row = reinterpret_cast<u64*>(out + base + (size_t)p * PDIM + q0);
        *reinterpret_cast<ulonglong2*>(row + tx * 2)      = make_ulonglong2(acc[i][0], acc[i][1]);
        *reinterpret_cast<ulonglong2*>(row + 32 + tx * 2) = make_ulonglong2(acc[i][2], acc[i][3]);
    }
}

extern "C" void kernel_launch(void* const* d_in, const int* in_sizes, int n_in,
                              void* d_out, int out_size)
{
    const float* iv00 = (const float*)d_in[0];   // intervals00 (256,32,2)
    const float* iv01 = (const float*)d_in[1];   // intervals01 (256,32,2)
    float* out = (float*)d_out;                  // (256,2,512,512) fp32

    dim3 grid(PDIM / TILE, PDIM / TILE, 512);
    hilbert_raster_kernel<<<grid, NTHREADS>>>(iv00, iv01, out);
}

// round 3
// speedup vs baseline: 1.9413x; 1.9413x over previous
#include <cuda_runtime.h>

#define PDIM     512
#define TILE     128
#define CH       16       // listC chunk held in smem
#define NTHREADS 256

__device__ __forceinline__ float clamp01f(float v) {
    return fminf(fmaxf(v, 0.0f), 1.0f);
}

// Factors (pixel units, see R1 derivation):
// img0: h=clamp(min(q+1-X, Y-q)), u=clamp(min(512-p-Y, X+1+p))
// img1: h=clamp(q+1-X),           u=clamp(Y-511+p)
__device__ __forceinline__ float h_of(int img, float X, float Y, float fq) {
    return (img == 0) ? clamp01f(fminf(fq + 1.0f - X, Y - fq))
                      : clamp01f(fq + 1.0f - X);
}
__device__ __forceinline__ float u_of(int img, float X, float Y, float fp) {
    return (img == 0) ? clamp01f(fminf(512.0f - fp - Y, X + 1.0f + fp))
                      : clamp01f(Y - 511.0f + fp);
}

__global__ __launch_bounds__(NTHREADS, 2)
void hilbert_raster_kernel(const float* __restrict__ iv00,
                           const float* __restrict__ iv01,
                           float* __restrict__ out)
{
    __shared__ float Xs[64], Ys[64];
    __shared__ float Arow[TILE], Bcol[TILE];
    __shared__ unsigned char listA[64], listB[64], listC[64];
    __shared__ int nA, nB, nC, cnt1;
    __shared__ float Us[CH][TILE], Hs[CH][TILE];

    const int t   = threadIdx.x;
    const int z   = blockIdx.z;          // batch*2 + img
    const int b   = z >> 1;
    const int img = z & 1;
    const int q0  = blockIdx.x * TILE;
    const int p0  = blockIdx.y * TILE;
    const float q0f = (float)q0, p0f = (float)p0;

    const float INV_SIDE = 325.94932345220167f;  // 1024/pi
    const int Keff = (img == 0) ? 64 : 32;

    if (t < 64) {
        const int k = t;
        float X = 1e9f, Y = -1e9f;
        if (k < 32) {
            X = iv00[(b * 32 + k) * 2 + 0] * INV_SIDE;
            Y = iv00[(b * 32 + k) * 2 + 1] * INV_SIDE;
        } else if (img == 0) {
            X = iv01[(b * 32 + (k - 32)) * 2 + 1] * INV_SIDE - 512.0f;
            Y = iv01[(b * 32 + (k - 32)) * 2 + 0] * INV_SIDE;
        }
        Xs[k] = X;
        Ys[k] = Y;
    }
    __syncthreads();

    // ---- classification (serial on thread 0: deterministic, ~64 iters) ----
    if (t == 0) {
        int na = 0, nb = 0, nc = 0, c1 = 0;
        for (int k = 0; k < Keff; ++k) {
            float X = Xs[k], Y = Ys[k];
            bool hz, ho, uz, uo;
            if (img == 0) {
                hz = (Y <= q0f) || (q0f + 127.0f <= X - 1.0f);
                ho = (X <= q0f) && (Y >= q0f + 128.0f);
                uz = (p0f >= 512.0f - Y) || (p0f + 127.0f <= -X - 1.0f);
                uo = (p0f >= -X) && (p0f + 127.0f <= 511.0f - Y);
            } else {
                hz = (q0f + 127.0f <= X - 1.0f);
                ho = (X <= q0f);
                uz = (p0f + 127.0f <= 511.0f - Y);
                uo = (p0f >= 512.0f - Y);
            }
            if (hz || uz) continue;
            else if (ho && uo) c1++;
            else if (ho) listA[na++] = (unsigned char)k;
            else if (uo) listB[nb++] = (unsigned char)k;
            else listC[nc++] = (unsigned char)k;
        }
        nA = na; nB = nb; nC = nc; cnt1 = c1;
    }
    __syncthreads();

    // ---- separable sums: A(p) over h==1 terms, B(q) over u==1 terms ----
    if (t < TILE) {
        float fp = (float)(p0 + t);
        float s = 0.0f;
        for (int i = 0; i < nA; ++i) {
            int k = listA[i];
            s += u_of(img, Xs[k], Ys[k], fp);
        }
        Arow[t] = s;
    } else {
        float fq = (float)(q0 + (t - TILE));
        float s = 0.0f;
        for (int i = 0; i < nB; ++i) {
            int k = listB[i];
            s += h_of(img, Xs[k], Ys[k], fq);
        }
        Bcol[t - TILE] = s;
    }
    __syncthreads();

    const int tx = t & 15;   // q direction
    const int ty = t >> 4;   // p direction

    float acc[8][8];
    #pragma unroll
    for (int i = 0; i < 8; ++i)
        #pragma unroll
        for (int j = 0; j < 8; ++j)
            acc[i][j] = 0.0f;

    // ---- outer products only for both-varying k ----
    const int nCl = nC;
    for (int cb = 0; cb < nCl; cb += CH) {
        const int cn = min(CH, nCl - cb);
        for (int idx = t; idx < cn * TILE; idx += NTHREADS) {
            int kk = idx >> 7;               // TILE == 128
            int j  = idx & (TILE - 1);
            int k  = listC[cb + kk];
            float X = Xs[k], Y = Ys[k];
            Us[kk][j] = u_of(img, X, Y, (float)(p0 + j));
            Hs[kk][j] = h_of(img, X, Y, (float)(q0 + j));
        }
        __syncthreads();

        #pragma unroll 4
        for (int kk = 0; kk < cn; ++kk) {
            float4 u0 = *reinterpret_cast<const float4*>(&Us[kk][ty * 4]);
            float4 u1 = *reinterpret_cast<const float4*>(&Us[kk][ty * 4 + 64]);
            float4 h0 = *reinterpret_cast<const float4*>(&Hs[kk][tx * 4]);
            float4 h1 = *reinterpret_cast<const float4*>(&Hs[kk][tx * 4 + 64]);
            float u[8] = {u0.x, u0.y, u0.z, u0.w, u1.x, u1.y, u1.z, u1.w};
            float h[8] = {h0.x, h0.y, h0.z, h0.w, h1.x, h1.y, h1.z, h1.w};
            #pragma unroll
            for (int i = 0; i < 8; ++i)
                #pragma unroll
                for (int j = 0; j < 8; ++j)
                    acc[i][j] = fmaf(u[i], h[j], acc[i][j]);
        }
        __syncthreads();
    }

    // ---- combine and store: out = acc + c0 + A(p) + B(q) ----
    const float c0 = (float)cnt1;
    float4 b0v = *reinterpret_cast<const float4*>(&Bcol[tx * 4]);
    float4 b1v = *reinterpret_cast<const float4*>(&Bcol[tx * 4 + 64]);
    const size_t base = (size_t)z * PDIM * PDIM;
    #pragma unroll
    for (int i = 0; i < 8; ++i) {
        int ri = ty * 4 + (i & 3) + ((i >= 4) ? 64 : 0);
        float a = c0 + Arow[ri];
        float* row = out + base + (size_t)(p0 + ri) * PDIM + q0;
        *reinterpret_cast<float4*>(row + tx * 4) =
            make_float4(acc[i][0] + a + b0v.x, acc[i][1] + a + b0v.y,
                        acc[i][2] + a + b0v.z, acc[i][3] + a + b0v.w);
        *reinterpret_cast<float4*>(row + 64 + tx * 4) =
            make_float4(acc[i][4] + a + b1v.x, acc[i][5] + a + b1v.y,
                        acc[i][6] + a + b1v.z, acc[i][7] + a + b1v.w);
    }
}

extern "C" void kernel_launch(void* const* d_in, const int* in_sizes, int n_in,
                              void* d_out, int out_size)
{
    const float* iv00 = (const float*)d_in[0];   // intervals00 (256,32,2)
    const float* iv01 = (const float*)d_in[1];   // intervals01 (256,32,2)
    float* out = (float*)d_out;                  // (256,2,512,512) fp32

    dim3 grid(PDIM / TILE, PDIM / TILE, 512);
    hilbert_raster_kernel<<<grid, NTHREADS>>>(iv00, iv01, out);
}

// round 4
// speedup vs baseline: 3.4738x; 1.7894x over previous
#include <cuda_runtime.h>

#define PDIM     512
#define TPQ      64     // tile q-width
#define TPP      128    // tile p-height
#define CH       16     // listC chunk in smem
#define NTHREADS 256

__device__ __forceinline__ float clamp01f(float v) {
    return fminf(fmaxf(v, 0.0f), 1.0f);
}

__device__ __forceinline__ float h_of(int img, float X, float Y, float fq) {
    return (img == 0) ? clamp01f(fminf(fq + 1.0f - X, Y - fq))
                      : clamp01f(fq + 1.0f - X);
}
__device__ __forceinline__ float u_of(int img, float X, float Y, float fp) {
    return (img == 0) ? clamp01f(fminf(512.0f - fp - Y, X + 1.0f + fp))
                      : clamp01f(Y - 511.0f + fp);
}

__global__ __launch_bounds__(NTHREADS, 4)
void hilbert_raster_kernel(const float* __restrict__ iv00,
                           const float* __restrict__ iv01,
                           float* __restrict__ out)
{
    __shared__ float Xs[64], Ys[64];
    __shared__ float Arow[TPP], Bcol[TPQ];
    __shared__ unsigned char listA[64], listB[64], listC[64];
    __shared__ int wCnt[2][4];          // [warp][cls-1]: counts of 1/A/B/C
    __shared__ float Us[CH][TPP], Hs[CH][TPQ];

    const int t   = threadIdx.x;
    const int z   = blockIdx.z;          // batch*2 + img
    const int b   = z >> 1;
    const int img = z & 1;
    const int q0  = blockIdx.x * TPQ;
    const int p0  = blockIdx.y * TPP;
    const float q0f = (float)q0, p0f = (float)p0;
    const float INV_SIDE = 325.94932345220167f;  // 1024/pi

    // ---- load endpoints + parallel classification (threads 0..63) ----
    int cls = 0;                 // 0 skip, 1 both-one, 2 A(h==1), 3 B(u==1), 4 C
    int myPrefix = 0;
    if (t < 64) {
        const int k = t;
        float X = 1e9f, Y = -1e9f;
        if (k < 32) {
            X = iv00[(b * 32 + k) * 2 + 0] * INV_SIDE;
            Y = iv00[(b * 32 + k) * 2 + 1] * INV_SIDE;
        } else if (img == 0) {
            X = iv01[(b * 32 + (k - 32)) * 2 + 1] * INV_SIDE - 512.0f;
            Y = iv01[(b * 32 + (k - 32)) * 2 + 0] * INV_SIDE;
        }
        Xs[k] = X;
        Ys[k] = Y;

        bool hz, ho, uz, uo;
        if (img == 0) {
            hz = (Y <= q0f) || (q0f + (TPQ - 1.0f) <= X - 1.0f);
            ho = (X <= q0f) && (Y >= q0f + (float)TPQ);
            uz = (p0f >= 512.0f - Y) || (p0f + (TPP - 1.0f) <= -X - 1.0f);
            uo = (p0f >= -X) && (p0f + (TPP - 1.0f) <= 511.0f - Y);
        } else {
            hz = (q0f + (TPQ - 1.0f) <= X - 1.0f);
            ho = (X <= q0f);
            uz = (p0f + (TPP - 1.0f) <= 511.0f - Y);
            uo = (p0f >= 512.0f - Y);
        }
        if (!(hz || uz)) {
            if (ho && uo) cls = 1;
            else if (ho) cls = 2;
            else if (uo) cls = 3;
            else cls = 4;
        }
        const unsigned full = 0xFFFFFFFFu;
        unsigned m1 = __ballot_sync(full, cls == 1);
        unsigned mA = __ballot_sync(full, cls == 2);
        unsigned mB = __ballot_sync(full, cls == 3);
        unsigned mC = __ballot_sync(full, cls == 4);
        int w = t >> 5;
        if ((t & 31) == 0) {
            wCnt[w][0] = __popc(m1); wCnt[w][1] = __popc(mA);
            wCnt[w][2] = __popc(mB); wCnt[w][3] = __popc(mC);
        }
        unsigned lt = (1u << (t & 31)) - 1u;
        if (cls == 2) myPrefix = __popc(mA & lt);
        else if (cls == 3) myPrefix = __popc(mB & lt);
        else if (cls == 4) myPrefix = __popc(mC & lt);
    }
    __syncthreads();

    const int nA = wCnt[0][1] + wCnt[1][1];
    const int nB = wCnt[0][2] + wCnt[1][2];
    const int nC = wCnt[0][3] + wCnt[1][3];
    const float c0 = (float)(wCnt[0][0] + wCnt[1][0]);

    if (t < 64 && cls >= 2) {
        int w = t >> 5;
        int base = (w == 1) ? wCnt[0][cls - 1] : 0;
        int pos = base + myPrefix;
        if (cls == 2) listA[pos] = (unsigned char)t;
        else if (cls == 3) listB[pos] = (unsigned char)t;
        else listC[pos] = (unsigned char)t;
    }
    __syncthreads();

    // ---- separable sums ----
    if (t < TPP) {
        float fp = (float)(p0 + t);
        float s = 0.0f;
        for (int i = 0; i < nA; ++i) {
            int k = listA[i];
            s += u_of(img, Xs[k], Ys[k], fp);
        }
        Arow[t] = s;
    } else if (t < TPP + TPQ) {
        float fq = (float)(q0 + (t - TPP));
        float s = 0.0f;
        for (int i = 0; i < nB; ++i) {
            int k = listB[i];
            s += h_of(img, Xs[k], Ys[k], fq);
        }
        Bcol[t - TPP] = s;
    }
    __syncthreads();

    const int tx = t & 15;   // q: 16 groups * 4 cols = 64
    const int ty = t >> 4;   // p: 16 groups * 8 rows = 128

    float acc[8][4];
    #pragma unroll
    for (int i = 0; i < 8; ++i)
        #pragma unroll
        for (int j = 0; j < 4; ++j)
            acc[i][j] = 0.0f;

    for (int cb = 0; cb < nC; cb += CH) {
        const int cn = min(CH, nC - cb);
        // fill factor tiles: cn*(TPP + TPQ) values
        for (int idx = t; idx < cn * TPP; idx += NTHREADS) {
            int kk = idx >> 7;                // TPP == 128
            int j  = idx & (TPP - 1);
            int k  = listC[cb + kk];
            Us[kk][j] = u_of(img, Xs[k], Ys[k], (float)(p0 + j));
        }
        for (int idx = t; idx < cn * TPQ; idx += NTHREADS) {
            int kk = idx >> 6;                // TPQ == 64
            int j  = idx & (TPQ - 1);
            int k  = listC[cb + kk];
            Hs[kk][j] = h_of(img, Xs[k], Ys[k], (float)(q0 + j));
        }
        __syncthreads();

        #pragma unroll 4
        for (int kk = 0; kk < cn; ++kk) {
            float4 u0 = *reinterpret_cast<const float4*>(&Us[kk][ty * 8]);
            float4 u1 = *reinterpret_cast<const float4*>(&Us[kk][ty * 8 + 4]);
            float4 h0 = *reinterpret_cast<const float4*>(&Hs[kk][tx * 4]);
            float u[8] = {u0.x, u0.y, u0.z, u0.w, u1.x, u1.y, u1.z, u1.w};
            float h[4] = {h0.x, h0.y, h0.z, h0.w};
            #pragma unroll
            for (int i = 0; i < 8; ++i)
                #pragma unroll
                for (int j = 0; j < 4; ++j)
                    acc[i][j] = fmaf(u[i], h[j], acc[i][j]);
        }
        __syncthreads();
    }

    // ---- combine and store ----
    float4 bv = *reinterpret_cast<const float4*>(&Bcol[tx * 4]);
    const size_t base = (size_t)z * PDIM * PDIM;
    #pragma unroll
    for (int i = 0; i < 8; ++i) {
        int ri = ty * 8 + i;
        float a = c0 + Arow[ri];
        float* row = out + base + (size_t)(p0 + ri) * PDIM + q0;
        *reinterpret_cast<float4*>(row + tx * 4) =
            make_float4(acc[i][0] + a + bv.x, acc[i][1] + a + bv.y,
                        acc[i][2] + a + bv.z, acc[i][3] + a + bv.w);
    }
}

extern "C" void kernel_launch(void* const* d_in, const int* in_sizes, int n_in,
                              void* d_out, int out_size)
{
    const float* iv00 = (const float*)d_in[0];   // intervals00 (256,32,2)
    const float* iv01 = (const float*)d_in[1];   // intervals01 (256,32,2)
    float* out = (float*)d_out;                  // (256,2,512,512) fp32

    dim3 grid(PDIM / TPQ, PDIM / TPP, 512);
    hilbert_raster_kernel<<<grid, NTHREADS>>>(iv00, iv01, out);
}

// round 5
// speedup vs baseline: 3.6026x; 1.0371x over previous
#include <cuda_runtime.h>

#define PDIM     512
#define TPQ      64
#define TPP      64
#define CH       16
#define NTHREADS 256

__device__ __forceinline__ float clamp01f(float v) {
    return fminf(fmaxf(v, 0.0f), 1.0f);
}

__device__ __forceinline__ float h_of(int img, float X, float Y, float fq) {
    return (img == 0) ? clamp01f(fminf(fq + 1.0f - X, Y - fq))
                      : clamp01f(fq + 1.0f - X);
}
__device__ __forceinline__ float u_of(int img, float X, float Y, float fp) {
    return (img == 0) ? clamp01f(fminf(512.0f - fp - Y, X + 1.0f + fp))
                      : clamp01f(Y - 511.0f + fp);
}

__device__ __forceinline__ void stcs4(float* p, float4 v) {
    asm volatile("st.global.cs.v4.f32 [%0], {%1,%2,%3,%4};"
                 :: "l"(p), "f"(v.x), "f"(v.y), "f"(v.z), "f"(v.w) : "memory");
}

__global__ __launch_bounds__(NTHREADS, 6)
void hilbert_raster_kernel(const float* __restrict__ iv00,
                           const float* __restrict__ iv01,
                           float* __restrict__ out)
{
    __shared__ float Xs[64], Ys[64];
    __shared__ float Arow[TPP], Bcol[TPQ];
    __shared__ unsigned char listA[64], listB[64], listC[64];
    __shared__ int wCnt[2][4];
    __shared__ float Us[CH][TPP], Hs[CH][TPQ];

    const int t   = threadIdx.x;
    const int z   = blockIdx.z;          // batch*2 + img
    const int b   = z >> 1;
    const int img = z & 1;
    const int q0  = blockIdx.x * TPQ;
    const int p0  = blockIdx.y * TPP;
    const float q0f = (float)q0, p0f = (float)p0;
    const float INV_SIDE = 325.94932345220167f;  // 1024/pi

    // ---- load endpoints + parallel classification (threads 0..63) ----
    int cls = 0;                 // 0 skip, 1 both-one, 2 A(h==1), 3 B(u==1), 4 C
    int myPrefix = 0;
    if (t < 64) {
        const int k = t;
        float X = 1e9f, Y = -1e9f;
        if (k < 32) {
            X = iv00[(b * 32 + k) * 2 + 0] * INV_SIDE;
            Y = iv00[(b * 32 + k) * 2 + 1] * INV_SIDE;
        } else if (img == 0) {
            X = iv01[(b * 32 + (k - 32)) * 2 + 1] * INV_SIDE - 512.0f;
            Y = iv01[(b * 32 + (k - 32)) * 2 + 0] * INV_SIDE;
        }
        Xs[k] = X;
        Ys[k] = Y;

        bool hz, ho, uz, uo;
        if (img == 0) {
            hz = (Y <= q0f) || (q0f + (TPQ - 1.0f) <= X - 1.0f);
            ho = (X <= q0f) && (Y >= q0f + (float)TPQ);
            uz = (p0f >= 512.0f - Y) || (p0f + (TPP - 1.0f) <= -X - 1.0f);
            uo = (p0f >= -X) && (p0f + (TPP - 1.0f) <= 511.0f - Y);
        } else {
            hz = (q0f + (TPQ - 1.0f) <= X - 1.0f);
            ho = (X <= q0f);
            uz = (p0f + (TPP - 1.0f) <= 511.0f - Y);
            uo = (p0f >= 512.0f - Y);
        }
        if (!(hz || uz)) {
            if (ho && uo) cls = 1;
            else if (ho) cls = 2;
            else if (uo) cls = 3;
            else cls = 4;
        }
        const unsigned full = 0xFFFFFFFFu;
        unsigned m1 = __ballot_sync(full, cls == 1);
        unsigned mA = __ballot_sync(full, cls == 2);
        unsigned mB = __ballot_sync(full, cls == 3);
        unsigned mC = __ballot_sync(full, cls == 4);
        int w = t >> 5;
        if ((t & 31) == 0) {
            wCnt[w][0] = __popc(m1); wCnt[w][1] = __popc(mA);
            wCnt[w][2] = __popc(mB); wCnt[w][3] = __popc(mC);
        }
        unsigned lt = (1u << (t & 31)) - 1u;
        if (cls == 2) myPrefix = __popc(mA & lt);
        else if (cls == 3) myPrefix = __popc(mB & lt);
        else if (cls == 4) myPrefix = __popc(mC & lt);
    }
    __syncthreads();

    const int nA = wCnt[0][1] + wCnt[1][1];
    const int nB = wCnt[0][2] + wCnt[1][2];
    const int nC = wCnt[0][3] + wCnt[1][3];
    const float c0 = (float)(wCnt[0][0] + wCnt[1][0]);

    if (t < 64 && cls >= 2) {
        int w = t >> 5;
        int base = (w == 1) ? wCnt[0][cls - 1] : 0;
        int pos = base + myPrefix;
        if (cls == 2) listA[pos] = (unsigned char)t;
        else if (cls == 3) listB[pos] = (unsigned char)t;
        else listC[pos] = (unsigned char)t;
    }
    __syncthreads();

    // ---- separable sums ----
    if (t < TPP) {
        float fp = (float)(p0 + t);
        float s = 0.0f;
        for (int i = 0; i < nA; ++i) {
            int k = listA[i];
            s += u_of(img, Xs[k], Ys[k], fp);
        }
        Arow[t] = s;
    } else if (t < TPP + TPQ) {
        float fq = (float)(q0 + (t - TPP));
        float s = 0.0f;
        for (int i = 0; i < nB; ++i) {
            int k = listB[i];
            s += h_of(img, Xs[k], Ys[k], fq);
        }
        Bcol[t - TPP] = s;
    }
    __syncthreads();

    const int tx = t & 15;   // q: 16 groups * 4 cols = 64
    const int ty = t >> 4;   // p: 16 groups * 4 rows = 64

    float acc[4][4];
    #pragma unroll
    for (int i = 0; i < 4; ++i)
        #pragma unroll
        for (int j = 0; j < 4; ++j)
            acc[i][j] = 0.0f;

    for (int cb = 0; cb < nC; cb += CH) {
        const int cn = min(CH, nC - cb);
        for (int idx = t; idx < cn * TPP; idx += NTHREADS) {
            int kk = idx >> 6;                // TPP == 64
            int j  = idx & (TPP - 1);
            int k  = listC[cb + kk];
            float X = Xs[k], Y = Ys[k];
            Us[kk][j] = u_of(img, X, Y, (float)(p0 + j));
            Hs[kk][j] = h_of(img, X, Y, (float)(q0 + j));
        }
        __syncthreads();

        #pragma unroll 4
        for (int kk = 0; kk < cn; ++kk) {
            float4 u0 = *reinterpret_cast<const float4*>(&Us[kk][ty * 4]);
            float4 h0 = *reinterpret_cast<const float4*>(&Hs[kk][tx * 4]);
            float u[4] = {u0.x, u0.y, u0.z, u0.w};
            float h[4] = {h0.x, h0.y, h0.z, h0.w};
            #pragma unroll
            for (int i = 0; i < 4; ++i)
                #pragma unroll
                for (int j = 0; j < 4; ++j)
                    acc[i][j] = fmaf(u[i], h[j], acc[i][j]);
        }
        __syncthreads();
    }

    // ---- combine and store (streaming) ----
    float4 bv = *reinterpret_cast<const float4*>(&Bcol[tx * 4]);
    const size_t base = (size_t)z * PDIM * PDIM;
    #pragma unroll
    for (int i = 0; i < 4; ++i) {
        int ri = ty * 4 + i;
        float a = c0 + Arow[ri];
        float* row = out + base + (size_t)(p0 + ri) * PDIM + q0;
        stcs4(row + tx * 4,
              make_float4(acc[i][0] + a + bv.x, acc[i][1] + a + bv.y,
                          acc[i][2] + a + bv.z, acc[i][3] + a + bv.w));
    }
}

extern "C" void kernel_launch(void* const* d_in, const int* in_sizes, int n_in,
                              void* d_out, int out_size)
{
    const float* iv00 = (const float*)d_in[0];   // intervals00 (256,32,2)
    const float* iv01 = (const float*)d_in[1];   // intervals01 (256,32,2)
    float* out = (float*)d_out;                  // (256,2,512,512) fp32

    dim3 grid(PDIM / TPQ, PDIM / TPP, 512);
    hilbert_raster_kernel<<<grid, NTHREADS>>>(iv00, iv01, out);
}